// round 16
// baseline (speedup 1.0000x reference)
#include <cuda_runtime.h>
#include <math.h>
#include <stdint.h>

#define T_  2048
#define C_  768
#define NH_ 12
#define HS_ 64
#define S_  1023
#define R_  (T_*NH_)
#define SCALE_ 0.125f

// ---------------- scratch ----------------
__device__ float g_q [T_*C_];
__device__ float g_k [T_*C_];
__device__ float g_v [T_*C_];
__device__ float g_G [(size_t)2*R_*128];   // two K-split partials
__device__ uint32_t g_Wfh[(size_t)2048*128];
__device__ uint32_t g_Wfl[(size_t)2048*128];
__device__ uint32_t g_Wqh[384*C_], g_Wql[384*C_];
__device__ uint32_t g_Wkh[384*C_], g_Wkl[384*C_];
__device__ uint32_t g_Wvh[384*C_], g_Wvl[384*C_];
__device__ uint32_t g_Wch[384*C_], g_Wcl[384*C_];
__device__ float g_Kt[(size_t)NH_*T_*HS_];
__device__ float g_Vt[(size_t)NH_*T_*HS_];
__device__ float g_Ks[(size_t)NH_*S_*HS_];
__device__ float g_Vs[(size_t)NH_*S_*HS_];
__device__ uint32_t g_Kph[(size_t)NH_*1024*32];
__device__ uint32_t g_Kpl[(size_t)NH_*1024*32];
__device__ uint32_t g_Vph[(size_t)NH_*512*64];
__device__ uint32_t g_Vpl[(size_t)NH_*512*64];
__device__ float g_CT[2*NH_*8*HS_];
__device__ float g_att[T_*C_];

// ---------------- helpers ----------------
__device__ __forceinline__ uint32_t smem_u32(const void* p) {
    uint32_t a;
    asm("{ .reg .u64 t; cvta.to.shared.u64 t, %1; cvt.u32.u64 %0, t; }" : "=r"(a) : "l"(p));
    return a;
}
__device__ __forceinline__ uint32_t pk_bf2(float x0, float x1) {
    uint32_t r;
    asm("cvt.rn.bf16x2.f32 %0, %1, %2;" : "=r"(r) : "f"(x1), "f"(x0));
    return r;
}
__device__ __forceinline__ void split2(float x0, float x1, uint32_t& hi, uint32_t& lo) {
    hi = pk_bf2(x0, x1);
    float h0 = __uint_as_float(hi << 16);
    float h1 = __uint_as_float(hi & 0xFFFF0000u);
    lo = pk_bf2(x0 - h0, x1 - h1);
}
__device__ __forceinline__ void cp_async16(uint32_t dst, const void* src) {
    asm volatile("cp.async.ca.shared.global [%0], [%1], 16;" :: "r"(dst), "l"(src) : "memory");
}
#define CP_COMMIT() asm volatile("cp.async.commit_group;" ::: "memory")
#define CP_WAIT1()  asm volatile("cp.async.wait_group 1;" ::: "memory")
#define CP_WAIT0()  asm volatile("cp.async.wait_group 0;" ::: "memory")

__device__ __forceinline__ void mma_bf16(float* c, uint32_t a0, uint32_t a1,
                                         uint32_t a2, uint32_t a3,
                                         uint32_t b0, uint32_t b1) {
    asm volatile(
        "mma.sync.aligned.m16n8k16.row.col.f32.bf16.bf16.f32 "
        "{%0,%1,%2,%3}, {%4,%5,%6,%7}, {%8,%9}, {%0,%1,%2,%3};"
        : "+f"(c[0]), "+f"(c[1]), "+f"(c[2]), "+f"(c[3])
        : "r"(a0), "r"(a1), "r"(a2), "r"(a3), "r"(b0), "r"(b1));
}

// ---------------- prep kernels ----------------
__global__ void split_w4(const float* __restrict__ Wq, const float* __restrict__ Wk,
                         const float* __restrict__ Wv, const float* __restrict__ Wc,
                         uint32_t* __restrict__ Wqh, uint32_t* __restrict__ Wql,
                         uint32_t* __restrict__ Wkh, uint32_t* __restrict__ Wkl,
                         uint32_t* __restrict__ Wvh, uint32_t* __restrict__ Wvl,
                         uint32_t* __restrict__ Wch, uint32_t* __restrict__ Wcl) {
    int i = blockIdx.x * 256 + threadIdx.x;
    if (i >= 384 * C_) return;
    int sel = blockIdx.y;
    const float* W = (sel == 0) ? Wq : (sel == 1) ? Wk : (sel == 2) ? Wv : Wc;
    uint32_t* Whi = (sel == 0) ? Wqh : (sel == 1) ? Wkh : (sel == 2) ? Wvh : Wch;
    uint32_t* Wlo = (sel == 0) ? Wql : (sel == 1) ? Wkl : (sel == 2) ? Wvl : Wcl;
    int kr = i / C_, n = i - kr * C_;
    float x0 = W[(size_t)(2 * kr) * C_ + n];
    float x1 = W[(size_t)(2 * kr + 1) * C_ + n];
    uint32_t hi, lo; split2(x0, x1, hi, lo);
    Whi[i] = hi; Wlo[i] = lo;
}
__global__ void split_wf(const float* __restrict__ Wks, const float* __restrict__ Wvs,
                         uint32_t* __restrict__ Whi, uint32_t* __restrict__ Wlo) {
    int i = blockIdx.x * 256 + threadIdx.x;
    int kr = i >> 7, n = i & 127;
    int r0 = 2 * kr, r1 = 2 * kr + 1;
    float x0 = (n < 64) ? Wks[(size_t)r0 * 64 + n] : Wvs[(size_t)r0 * 64 + (n - 64)];
    float x1 = (n < 64) ? Wks[(size_t)r1 * 64 + n] : Wvs[(size_t)r1 * 64 + (n - 64)];
    uint32_t hi, lo; split2(x0, x1, hi, lo);
    Whi[i] = hi; Wlo[i] = lo;
}
__global__ void pack_kv(const float* __restrict__ Ks, const float* __restrict__ Vs,
                        uint32_t* __restrict__ Kph, uint32_t* __restrict__ Kpl,
                        uint32_t* __restrict__ Vph, uint32_t* __restrict__ Vpl) {
    int i = blockIdx.x * 256 + threadIdx.x;
    int h = i >> 15, rem = i & 32767;
    float x0, x1;
    if (blockIdx.y == 0) {
        int s = rem >> 5, dpr = rem & 31;
        x0 = 0.f; x1 = 0.f;
        if (s < S_) {
            const float* p = Ks + ((size_t)h * S_ + s) * 64 + 2 * dpr;
            x0 = p[0]; x1 = p[1];
        }
        uint32_t hi, lo; split2(x0, x1, hi, lo);
        Kph[i] = hi; Kpl[i] = lo;
    } else {
        int sr = rem >> 6, d = rem & 63;
        int s0 = 2 * sr, s1 = 2 * sr + 1;
        x0 = (s0 < S_) ? Vs[((size_t)h * S_ + s0) * 64 + d] : 0.f;
        x1 = (s1 < S_) ? Vs[((size_t)h * S_ + s1) * 64 + d] : 0.f;
        uint32_t hi, lo; split2(x0, x1, hi, lo);
        Vph[i] = hi; Vpl[i] = lo;
    }
}

// ---------------- generic bf16-split GEMM ----------------
#define GT_A0 0
#define GT_A1 34816
#define GT_B0 69632
#define GT_B1 104448
#define GT_SMEM 139264

template<int ACT, int BIAS>
__global__ __launch_bounds__(256)
void gemm_tc(const float* __restrict__ A, const uint32_t* __restrict__ Bhi,
             const uint32_t* __restrict__ Blo, const float* __restrict__ bias,
             float* __restrict__ C, int M, int N, int K)
{
    extern __shared__ char smem[];
    const uint32_t sb = smem_u32(smem);
    const int tid = threadIdx.x;
    const int wid = tid >> 5, lane = tid & 31;
    const int g = lane >> 2, l3 = lane & 3;
    const int bm = blockIdx.y * 128, bn = blockIdx.x * 128;
    const int r0 = wid * 16 + g, r1 = r0 + 8;
    const int nch = K >> 6;

    float acc[16][4];
    #pragma unroll
    for (int nt = 0; nt < 16; nt++)
        #pragma unroll
        for (int c = 0; c < 4; c++) acc[nt][c] = 0.f;

    auto stage = [&](int c, int buf) {
        uint32_t aB = sb + (buf ? GT_A1 : GT_A0);
        uint32_t bB = sb + (buf ? GT_B1 : GT_B0);
        #pragma unroll
        for (int m = 0; m < 8; m++) {
            int idx = tid + m * 256;
            int r = idx >> 4, q = idx & 15;
            cp_async16(aB + r * 272 + q * 16,
                       A + (size_t)(bm + r) * K + c * 64 + q * 4);
        }
        #pragma unroll
        for (int m = 0; m < 4; m++) {
            int f = tid + m * 256;
            int kr = f >> 5, q = f & 31;
            cp_async16(bB + kr * 544 + q * 16,
                       Bhi + (size_t)(c * 32 + kr) * N + bn + q * 4);
            cp_async16(bB + 17408 + kr * 544 + q * 16,
                       Blo + (size_t)(c * 32 + kr) * N + bn + q * 4);
        }
    };

    stage(0, 0); CP_COMMIT();

    for (int i = 0; i < nch; i++) {
        int buf = i & 1;
        if (i + 1 < nch) { stage(i + 1, buf ^ 1); CP_COMMIT(); CP_WAIT1(); }
        else CP_WAIT0();
        __syncthreads();
        const float* Ab = (const float*)(smem + (buf ? GT_A1 : GT_A0));
        const uint32_t* Bh = (const uint32_t*)(smem + (buf ? GT_B1 : GT_B0));
        const uint32_t* Bl = Bh + 17408 / 4;
        #pragma unroll
        for (int kk = 0; kk < 4; kk++) {
            int kb = kk * 16 + 2 * l3;
            float2 xa = *(const float2*)&Ab[r0 * 68 + kb];
            float2 xb = *(const float2*)&Ab[r0 * 68 + kb + 8];
            float2 xc = *(const float2*)&Ab[r1 * 68 + kb];
            float2 xd = *(const float2*)&Ab[r1 * 68 + kb + 8];
            uint32_t a0h, a0l, a1h, a1l, a2h, a2l, a3h, a3l;
            split2(xa.x, xa.y, a0h, a0l);
            split2(xc.x, xc.y, a1h, a1l);
            split2(xb.x, xb.y, a2h, a2l);
            split2(xd.x, xd.y, a3h, a3l);
            const uint32_t* bh0 = Bh + (kk * 8 + l3) * 136 + g;
            const uint32_t* bl0 = Bl + (kk * 8 + l3) * 136 + g;
            #pragma unroll
            for (int nt = 0; nt < 16; nt++) {
                uint32_t bh_0 = bh0[nt * 8], bh_1 = bh0[4 * 136 + nt * 8];
                uint32_t bl_0 = bl0[nt * 8], bl_1 = bl0[4 * 136 + nt * 8];
                mma_bf16(acc[nt], a0h, a1h, a2h, a3h, bh_0, bh_1);
                mma_bf16(acc[nt], a0h, a1h, a2h, a3h, bl_0, bl_1);
                mma_bf16(acc[nt], a0l, a1l, a2l, a3l, bh_0, bh_1);
            }
        }
        __syncthreads();
    }

    #pragma unroll
    for (int nt = 0; nt < 16; nt++) {
        int col = bn + nt * 8 + 2 * l3;
        float z0 = acc[nt][0], z1 = acc[nt][1], z2 = acc[nt][2], z3 = acc[nt][3];
        if (BIAS) { z0 += bias[col]; z1 += bias[col + 1]; z2 += bias[col]; z3 += bias[col + 1]; }
        if (ACT) {
            z0 = (z0 > 0.f) ? (z0 + 1.f) : expf(z0);
            z1 = (z1 > 0.f) ? (z1 + 1.f) : expf(z1);
            z2 = (z2 > 0.f) ? (z2 + 1.f) : expf(z2);
            z3 = (z3 > 0.f) ? (z3 + 1.f) : expf(z3);
        }
        *(float2*)(C + (size_t)(bm + r0) * N + col) = make_float2(z0, z1);
        *(float2*)(C + (size_t)(bm + r1) * N + col) = make_float2(z2, z3);
    }
}

// ---------------- fused QKV GEMM ----------------
__global__ __launch_bounds__(256)
void gemm_qkv(const float* __restrict__ A,
              const uint32_t* __restrict__ Bh0, const uint32_t* __restrict__ Bl0,
              const uint32_t* __restrict__ Bh1, const uint32_t* __restrict__ Bl1,
              const uint32_t* __restrict__ Bh2, const uint32_t* __restrict__ Bl2,
              float* __restrict__ C0, float* __restrict__ C1, float* __restrict__ C2)
{
    extern __shared__ char smem[];
    const uint32_t sb = smem_u32(smem);
    const int tid = threadIdx.x;
    const int wid = tid >> 5, lane = tid & 31;
    const int g = lane >> 2, l3 = lane & 3;
    const int sel = blockIdx.x / 6;
    const uint32_t* Bhi = (sel == 0) ? Bh0 : (sel == 1) ? Bh1 : Bh2;
    const uint32_t* Blo = (sel == 0) ? Bl0 : (sel == 1) ? Bl1 : Bl2;
    float* C = (sel == 0) ? C0 : (sel == 1) ? C1 : C2;
    const bool act = sel < 2;
    const int bm = blockIdx.y * 128, bn = (blockIdx.x % 6) * 128;
    const int r0 = wid * 16 + g, r1 = r0 + 8;
    const int N = C_, K = C_, nch = K >> 6;

    float acc[16][4];
    #pragma unroll
    for (int nt = 0; nt < 16; nt++)
        #pragma unroll
        for (int c = 0; c < 4; c++) acc[nt][c] = 0.f;

    auto stage = [&](int c, int buf) {
        uint32_t aB = sb + (buf ? GT_A1 : GT_A0);
        uint32_t bB = sb + (buf ? GT_B1 : GT_B0);
        #pragma unroll
        for (int m = 0; m < 8; m++) {
            int idx = tid + m * 256;
            int r = idx >> 4, q = idx & 15;
            cp_async16(aB + r * 272 + q * 16,
                       A + (size_t)(bm + r) * K + c * 64 + q * 4);
        }
        #pragma unroll
        for (int m = 0; m < 4; m++) {
            int f = tid + m * 256;
            int kr = f >> 5, q = f & 31;
            cp_async16(bB + kr * 544 + q * 16,
                       Bhi + (size_t)(c * 32 + kr) * N + bn + q * 4);
            cp_async16(bB + 17408 + kr * 544 + q * 16,
                       Blo + (size_t)(c * 32 + kr) * N + bn + q * 4);
        }
    };

    stage(0, 0); CP_COMMIT();

    for (int i = 0; i < nch; i++) {
        int buf = i & 1;
        if (i + 1 < nch) { stage(i + 1, buf ^ 1); CP_COMMIT(); CP_WAIT1(); }
        else CP_WAIT0();
        __syncthreads();
        const float* Ab = (const float*)(smem + (buf ? GT_A1 : GT_A0));
        const uint32_t* Bh = (const uint32_t*)(smem + (buf ? GT_B1 : GT_B0));
        const uint32_t* Bl = Bh + 17408 / 4;
        #pragma unroll
        for (int kk = 0; kk < 4; kk++) {
            int kb = kk * 16 + 2 * l3;
            float2 xa = *(const float2*)&Ab[r0 * 68 + kb];
            float2 xb = *(const float2*)&Ab[r0 * 68 + kb + 8];
            float2 xc = *(const float2*)&Ab[r1 * 68 + kb];
            float2 xd = *(const float2*)&Ab[r1 * 68 + kb + 8];
            uint32_t a0h, a0l, a1h, a1l, a2h, a2l, a3h, a3l;
            split2(xa.x, xa.y, a0h, a0l);
            split2(xc.x, xc.y, a1h, a1l);
            split2(xb.x, xb.y, a2h, a2l);
            split2(xd.x, xd.y, a3h, a3l);
            const uint32_t* bh0 = Bh + (kk * 8 + l3) * 136 + g;
            const uint32_t* bl0 = Bl + (kk * 8 + l3) * 136 + g;
            #pragma unroll
            for (int nt = 0; nt < 16; nt++) {
                uint32_t bh_0 = bh0[nt * 8], bh_1 = bh0[4 * 136 + nt * 8];
                uint32_t bl_0 = bl0[nt * 8], bl_1 = bl0[4 * 136 + nt * 8];
                mma_bf16(acc[nt], a0h, a1h, a2h, a3h, bh_0, bh_1);
                mma_bf16(acc[nt], a0h, a1h, a2h, a3h, bl_0, bl_1);
                mma_bf16(acc[nt], a0l, a1l, a2l, a3l, bh_0, bh_1);
            }
        }
        __syncthreads();
    }

    #pragma unroll
    for (int nt = 0; nt < 16; nt++) {
        int col = bn + nt * 8 + 2 * l3;
        float z0 = acc[nt][0], z1 = acc[nt][1], z2 = acc[nt][2], z3 = acc[nt][3];
        if (act) {
            z0 = (z0 > 0.f) ? (z0 + 1.f) : expf(z0);
            z1 = (z1 > 0.f) ? (z1 + 1.f) : expf(z1);
            z2 = (z2 > 0.f) ? (z2 + 1.f) : expf(z2);
            z3 = (z3 > 0.f) ? (z3 + 1.f) : expf(z3);
        }
        *(float2*)(C + (size_t)(bm + r0) * N + col) = make_float2(z0, z1);
        *(float2*)(C + (size_t)(bm + r1) * N + col) = make_float2(z2, z3);
    }
}

// ---------------- gproj: R10 proven shape, K-split x2 ----------------
#define GP_K0 0
#define GP_B0 34816
#define GP_B1 69632
#define GP_SMEM 104448

__global__ __launch_bounds__(256)
void gproj_mma(const float* __restrict__ kmat, const float* __restrict__ vmat,
               const uint32_t* __restrict__ Wfh, const uint32_t* __restrict__ Wfl,
               float* __restrict__ G)
{
    extern __shared__ char smem[];
    const uint32_t sb = smem_u32(smem);
    const int tid = threadIdx.x;
    const int wid = tid >> 5, lane = tid & 31;
    const int g = lane >> 2, l3 = lane & 3;
    const int rbase = blockIdx.x * 128;
    const int cbase = blockIdx.y * 32;
    float* Gout = G + (size_t)blockIdx.y * R_ * 128;
    const int r0 = wid * 16 + g, r1 = r0 + 8;

    auto stageB = [&](int c, int buf) {
        uint32_t bB = sb + (buf ? GP_B1 : GP_B0);
        #pragma unroll
        for (int m = 0; m < 4; m++) {
            int f = tid + m * 256;
            int kr = f >> 5, q = f & 31;
            cp_async16(bB + kr * 544 + q * 16,
                       Wfh + (size_t)((cbase + c) * 32 + kr) * 128 + q * 4);
            cp_async16(bB + 17408 + kr * 544 + q * 16,
                       Wfl + (size_t)((cbase + c) * 32 + kr) * 128 + q * 4);
        }
    };

    #pragma unroll
    for (int m = 0; m < 8; m++) {
        int idx = tid + m * 256;
        int r = idx >> 4, q = idx & 15;
        cp_async16(sb + GP_K0 + r * 272 + q * 16,
                   kmat + (size_t)(rbase + r) * 64 + q * 4);
    }
    stageB(0, 0); CP_COMMIT();

    float2 v0a[4], v0b[4], v1a[4], v1b[4];
    {
        const float* vp0 = vmat + (size_t)(rbase + r0) * 64;
        const float* vp1 = vmat + (size_t)(rbase + r1) * 64;
        #pragma unroll
        for (int kk = 0; kk < 4; kk++) {
            v0a[kk] = *(const float2*)(vp0 + kk * 16 + 2 * l3);
            v0b[kk] = *(const float2*)(vp0 + kk * 16 + 2 * l3 + 8);
            v1a[kk] = *(const float2*)(vp1 + kk * 16 + 2 * l3);
            v1b[kk] = *(const float2*)(vp1 + kk * 16 + 2 * l3 + 8);
        }
    }

    float acc[16][4];
    #pragma unroll
    for (int nt = 0; nt < 16; nt++)
        #pragma unroll
        for (int c = 0; c < 4; c++) acc[nt][c] = 0.f;

    const float* Ksm = (const float*)(smem + GP_K0);

    for (int i = 0; i < 32; i++) {
        int buf = i & 1;
        if (i < 31) { stageB(i + 1, buf ^ 1); CP_COMMIT(); CP_WAIT1(); }
        else CP_WAIT0();
        __syncthreads();
        const uint32_t* Bh = (const uint32_t*)(smem + (buf ? GP_B1 : GP_B0));
        const uint32_t* Bl = Bh + 17408 / 4;
        float k0 = Ksm[r0 * 68 + cbase + i];
        float k1 = Ksm[r1 * 68 + cbase + i];
        #pragma unroll
        for (int kk = 0; kk < 4; kk++) {
            uint32_t a0h, a0l, a1h, a1l, a2h, a2l, a3h, a3l;
            split2(k0 * v0a[kk].x, k0 * v0a[kk].y, a0h, a0l);
            split2(k1 * v1a[kk].x, k1 * v1a[kk].y, a1h, a1l);
            split2(k0 * v0b[kk].x, k0 * v0b[kk].y, a2h, a2l);
            split2(k1 * v1b[kk].x, k1 * v1b[kk].y, a3h, a3l);
            const uint32_t* bh0 = Bh + (kk * 8 + l3) * 136 + g;
            const uint32_t* bl0 = Bl + (kk * 8 + l3) * 136 + g;
            #pragma unroll
            for (int nt = 0; nt < 16; nt++) {
                uint32_t bh_0 = bh0[nt * 8], bh_1 = bh0[4 * 136 + nt * 8];
                uint32_t bl_0 = bl0[nt * 8], bl_1 = bl0[4 * 136 + nt * 8];
                mma_bf16(acc[nt], a0h, a1h, a2h, a3h, bh_0, bh_1);
                mma_bf16(acc[nt], a0h, a1h, a2h, a3h, bl_0, bl_1);
                mma_bf16(acc[nt], a0l, a1l, a2l, a3l, bh_0, bh_1);
            }
        }
        __syncthreads();
    }

    #pragma unroll
    for (int nt = 0; nt < 16; nt++) {
        int col = nt * 8 + 2 * l3;
        *(float2*)(Gout + (size_t)(rbase + r0) * 128 + col) = make_float2(acc[nt][0], acc[nt][1]);
        *(float2*)(Gout + (size_t)(rbase + r1) * 128 + col) = make_float2(acc[nt][2], acc[nt][3]);
    }
}

// ------- scan (sums two K-split partials) + hilevel -------
__global__ __launch_bounds__(64)
void scan_kernel(const float* __restrict__ G,
                 const float* __restrict__ bks, const float* __restrict__ bvs,
                 float* __restrict__ Kt, float* __restrict__ Vt,
                 float* __restrict__ Ksg, float* __restrict__ Vsg,
                 float* __restrict__ CT)
{
    const int d = threadIdx.x;
    const int chunk = blockIdx.x;
    const int h = blockIdx.y;
    const int map = blockIdx.z;
    const float bias = map ? bvs[d] : bks[d];
    float* tailp = map ? Vt : Kt;
    float* setp  = map ? Vsg : Ksg;
    const size_t HALF = (size_t)R_ * 128;

    float acc = 0.f, prev4 = 0.f;
    float prevl[7];
    #pragma unroll
    for (int i = 0; i < 7; i++) prevl[i] = 0.f;

    const int t0 = chunk * 256;
    for (int tb = 0; tb < 256; tb += 8) {
        float xv[8];
        #pragma unroll
        for (int i = 0; i < 8; i++) {
            size_t o = ((size_t)((t0 + tb + i) * NH_ + h)) * 128 + map * 64 + d;
            xv[i] = G[o] + G[o + HALF];
        }
        #pragma unroll
        for (int i = 0; i < 8; i++) {
            const int t = t0 + tb + i;
            acc += xv[i];
            tailp[((size_t)h * T_ + t) * 64 + d] = acc - prev4 + bias;
            const int tp1 = t + 1;
            if ((tp1 & 3) == 0) prev4 = acc;
            #pragma unroll
            for (int li = 0; li < 7; li++) {
                const int l = li + 2;
                if ((tp1 & ((1 << l) - 1)) == 0) {
                    const int offl = 1024 - (4096 >> l);
                    const int gb = (tp1 >> l) - 1;
                    setp[((size_t)h * S_ + offl + gb) * 64 + d] = acc - prevl[li] + bias;
                    prevl[li] = acc;
                }
            }
        }
    }
    CT[((size_t)(map * NH_ + h) * 8 + chunk) * 64 + d] = acc;
}

__global__ __launch_bounds__(64)
void hilevel_kernel(const float* __restrict__ CT,
                    const float* __restrict__ bks, const float* __restrict__ bvs,
                    float* __restrict__ Ksg, float* __restrict__ Vsg)
{
    const int d = threadIdx.x;
    const int h = blockIdx.x;
    const int map = blockIdx.y;
    const float bias = map ? bvs[d] : bks[d];
    float* setp = map ? Vsg : Ksg;
    const float* ct = CT + ((size_t)(map * NH_ + h) * 8) * 64 + d;
    float c[8];
    #pragma unroll
    for (int i = 0; i < 8; i++) c[i] = ct[i * 64];
    #pragma unroll
    for (int b = 0; b < 4; b++)
        setp[((size_t)h * S_ + 1016 + b) * 64 + d] = c[2*b] + c[2*b+1] + bias;
    #pragma unroll
    for (int b = 0; b < 2; b++)
        setp[((size_t)h * S_ + 1020 + b) * 64 + d] =
            c[4*b] + c[4*b+1] + c[4*b+2] + c[4*b+3] + bias;
    setp[((size_t)h * S_ + 1022) * 64 + d] =
        c[0]+c[1]+c[2]+c[3]+c[4]+c[5]+c[6]+c[7] + bias;
}

// ---------------- attention: 32 t-rows per CTA, causal chunk skipping ----------------
#define AT_QS   0
#define AT_ENDS 8192
#define AT_TW   12288
#define AT_LS   12416
#define AT_BUF  143744
#define AT_BSTR 36864
#define AT_SMEM 217472
#define LSTR 1026

__global__ __launch_bounds__(256)
void attn_mma(const float* __restrict__ q,
              const uint32_t* __restrict__ Kph, const uint32_t* __restrict__ Kpl,
              const uint32_t* __restrict__ Vph, const uint32_t* __restrict__ Vpl,
              const float* __restrict__ Kt, const float* __restrict__ Vt,
              float* __restrict__ attout)
{
    extern __shared__ char smem[];
    const uint32_t sb = smem_u32(smem);
    float* Qs = (float*)(smem + AT_QS);
    int* endsI = (int*)(smem + AT_ENDS);
    float* tailw = (float*)(smem + AT_TW);
    float* Ls = (float*)(smem + AT_LS);

    const int h = blockIdx.y;
    // heavy blocks (large t0, more active chunks) scheduled first
    const int t0 = ((int)gridDim.x - 1 - (int)blockIdx.x) * 32;
    const int tid = threadIdx.x;
    const int wid = tid >> 5, lane = tid & 31;
    const int g = lane >> 2, l3 = lane & 3;

    // active-chunk list: chunk c is fully masked when its minimum set-end
    // exceeds t0+32.  min ends per chunk: {4, 516, 1028, 1540, 8, 1032, 16, 32}
    // NOTE: chunk 7 (minend 32) is active for every t0, and it contains the
    // tail column s=1023, so the softmax segment loops cover the tail too.
    const int tmax = t0 + 32;
    int cl[8];
    int nc = 0;
    {
        const int minend[8] = {4, 516, 1028, 1540, 8, 1032, 16, 32};
        #pragma unroll
        for (int c = 0; c < 8; c++)
            if (minend[c] <= tmax) cl[nc++] = c;
    }

    #pragma unroll
    for (int it = 0; it < 8; it++) {
        int idx = tid + it * 256;
        Qs[idx] = q[(size_t)(t0 + (idx >> 6)) * C_ + h * 64 + (idx & 63)];
    }
    for (int s = tid; s < 1024; s += 256) {
        if (s < S_) {
            int off = 0, n = 512, l = 2;
            while (s >= off + n) { off += n; n >>= 1; l++; }
            endsI[s] = (s - off + 1) << l;
        } else endsI[s] = 0x7fffffff;
    }

    auto stageK = [&](int c, int buf) {
        uint32_t base = sb + AT_BUF + buf * AT_BSTR;
        #pragma unroll
        for (int m = 0; m < 4; m++) {
            int idx = tid + m * 256;
            int row = idx >> 3, q16 = idx & 7;
            size_t gro = ((size_t)h * 1024 + c * 128 + row) * 32 + q16 * 4;
            cp_async16(base + row * 144 + q16 * 16, Kph + gro);
            cp_async16(base + 18432 + row * 144 + q16 * 16, Kpl + gro);
        }
    };
    auto stageV = [&](int c, int buf) {
        uint32_t base = sb + AT_BUF + buf * AT_BSTR;
        #pragma unroll
        for (int m = 0; m < 4; m++) {
            int idx = tid + m * 256;
            int row = idx >> 4, q16 = idx & 15;
            size_t gro = ((size_t)h * 512 + c * 64 + row) * 64 + q16 * 4;
            cp_async16(base + row * 288 + q16 * 16, Vph + gro);
            cp_async16(base + 18432 + row * 288 + q16 * 16, Vpl + gro);
        }
    };

    stageK(cl[0], 0); CP_COMMIT();
    __syncthreads();

    uint32_t qa_h[2][4][4], qa_l[2][4][4];
    #pragma unroll
    for (int rt = 0; rt < 2; rt++) {
        int rb = rt * 16;
        #pragma unroll
        for (int kk = 0; kk < 4; kk++) {
            int kb = kk * 16 + 2 * l3;
            float2 xa = *(const float2*)&Qs[(rb + g) * 64 + kb];
            float2 xb = *(const float2*)&Qs[(rb + g) * 64 + kb + 8];
            float2 xc = *(const float2*)&Qs[(rb + g + 8) * 64 + kb];
            float2 xd = *(const float2*)&Qs[(rb + g + 8) * 64 + kb + 8];
            split2(xa.x, xa.y, qa_h[rt][kk][0], qa_l[rt][kk][0]);
            split2(xc.x, xc.y, qa_h[rt][kk][1], qa_l[rt][kk][1]);
            split2(xb.x, xb.y, qa_h[rt][kk][2], qa_l[rt][kk][2]);
            split2(xd.x, xd.y, qa_h[rt][kk][3], qa_l[rt][kk][3]);
        }
    }

    // ---- logits over active chunks ----
    for (int ci = 0; ci < nc; ci++) {
        int c = cl[ci];
        int buf = ci & 1;
        if (ci + 1 < nc) { stageK(cl[ci + 1], buf ^ 1); CP_COMMIT(); CP_WAIT1(); }
        else CP_WAIT0();
        __syncthreads();
        const uint32_t* Kh = (const uint32_t*)(smem + AT_BUF + buf * AT_BSTR);
        const uint32_t* Kl = Kh + 18432 / 4;
        #pragma unroll
        for (int nt2 = 0; nt2 < 2; nt2++) {
            int nt = wid * 2 + nt2;
            float acc4[2][4] = {{0.f,0.f,0.f,0.f},{0.f,0.f,0.f,0.f}};
            #pragma unroll
            for (int kk = 0; kk < 4; kk++) {
                const uint32_t* kr = Kh + (nt * 8 + g) * 36 + kk * 8 + l3;
                const uint32_t* krl = Kl + (nt * 8 + g) * 36 + kk * 8 + l3;
                uint32_t bh0 = kr[0], bh1 = kr[4];
                uint32_t bl0 = krl[0], bl1 = krl[4];
                #pragma unroll
                for (int rt = 0; rt < 2; rt++) {
                    mma_bf16(acc4[rt], qa_h[rt][kk][0], qa_h[rt][kk][1], qa_h[rt][kk][2], qa_h[rt][kk][3], bh0, bh1);
                    mma_bf16(acc4[rt], qa_h[rt][kk][0], qa_h[rt][kk][1], qa_h[rt][kk][2], qa_h[rt][kk][3], bl0, bl1);
                    mma_bf16(acc4[rt], qa_l[rt][kk][0], qa_l[rt][kk][1], qa_l[rt][kk][2], qa_l[rt][kk][3], bh0, bh1);
                }
            }
            int s0 = c * 128 + nt * 8 + 2 * l3;
            int e0 = endsI[s0], e1 = endsI[s0 + 1];
            #pragma unroll
            for (int rt = 0; rt < 2; rt++) {
                int ra = rt * 16 + g, rb = ra + 8;
                Ls[ra * LSTR + s0]     = (e0 <= t0 + ra + 1) ? acc4[rt][0] * SCALE_ : -1e30f;
                Ls[ra * LSTR + s0 + 1] = (e1 <= t0 + ra + 1) ? acc4[rt][1] * SCALE_ : -1e30f;
                Ls[rb * LSTR + s0]     = (e0 <= t0 + rb + 1) ? acc4[rt][2] * SCALE_ : -1e30f;
                Ls[rb * LSTR + s0 + 1] = (e1 <= t0 + rb + 1) ? acc4[rt][3] * SCALE_ : -1e30f;
            }
        }
        __syncthreads();
    }

    stageV(cl[0], 0); CP_COMMIT();

    // ---- tail logits (overwrite the masked value at column 1023) ----
    {
        #pragma unroll
        for (int ti = 0; ti < 4; ti++) {
            int tq = wid * 4 + ti;
            const float* ktp = Kt + ((size_t)h * T_ + t0 + tq) * 64;
            float p = Qs[tq * 64 + lane] * ktp[lane]
                    + Qs[tq * 64 + lane + 32] * ktp[lane + 32];
            #pragma unroll
            for (int o = 16; o; o >>= 1) p += __shfl_xor_sync(0xffffffffu, p, o);
            if (lane == 0) Ls[tq * LSTR + 1023] = p * SCALE_;
        }
    }
    __syncthreads();

    // ---- softmax over active-chunk columns (chunk 7 is always active and
    //      contains the tail column 1023; skipped-chunk columns would exp to
    //      exactly 0.0, an additive identity, so this is bit-identical) ----
    {
        for (int ti = 0; ti < 4; ti++) {
            float* row = Ls + (wid * 4 + ti) * LSTR;
            float m = -1e30f;
            for (int ci = 0; ci < nc; ci++) {
                const float* seg = row + cl[ci] * 128;
                for (int s = lane; s < 128; s += 32) m = fmaxf(m, seg[s]);
            }
            #pragma unroll
            for (int o = 16; o; o >>= 1) m = fmaxf(m, __shfl_xor_sync(0xffffffffu, m, o));
            float sum = 0.f;
            for (int ci = 0; ci < nc; ci++) {
                float* seg = row + cl[ci] * 128;
                for (int s = lane; s < 128; s += 32) {
                    float e = expf(seg[s] - m);
                    seg[s] = e;
                    sum += e;
                }
            }
            #pragma unroll
            for (int o = 16; o; o >>= 1) sum += __shfl_xor_sync(0xffffffffu, sum, o);
            float inv = 1.f / sum;
            for (int ci = 0; ci < nc; ci++) {
                float* seg = row + cl[ci] * 128;
                for (int s = lane; s < 128; s += 32) seg[s] *= inv;
            }
        }
    }
    __syncthreads();
    if (tid < 32) { tailw[tid] = Ls[tid * LSTR + 1023]; Ls[tid * LSTR + 1023] = 0.f; }
    __syncthreads();

    // ---- AV over active chunks (skipped chunks contribute exactly 0) ----
    float oacc[2][4] = {{0.f,0.f,0.f,0.f},{0.f,0.f,0.f,0.f}};
    for (int ci = 0; ci < nc; ci++) {
        int c = cl[ci];
        int buf = ci & 1;
        if (ci + 1 < nc) { stageV(cl[ci + 1], buf ^ 1); CP_COMMIT(); CP_WAIT1(); }
        else CP_WAIT0();
        __syncthreads();
        const uint32_t* Vh = (const uint32_t*)(smem + AT_BUF + buf * AT_BSTR);
        const uint32_t* Vl = Vh + 18432 / 4;
        #pragma unroll
        for (int kk = 0; kk < 8; kk++) {
            int kb = c * 128 + kk * 16 + 2 * l3;
            int d0 = wid * 8 + g;
            uint32_t bh0 = Vh[(kk * 8 + l3) * 72 + d0];
            uint32_t bh1 = Vh[(kk * 8 + l3 + 4) * 72 + d0];
            uint32_t bl0 = Vl[(kk * 8 + l3) * 72 + d0];
            uint32_t bl1 = Vl[(kk * 8 + l3 + 4) * 72 + d0];
            #pragma unroll
            for (int rt = 0; rt < 2; rt++) {
                int rb = rt * 16;
                float2 pa = *(const float2*)&Ls[(rb + g) * LSTR + kb];
                float2 pb = *(const float2*)&Ls[(rb + g) * LSTR + kb + 8];
                float2 pc = *(const float2*)&Ls[(rb + g + 8) * LSTR + kb];
                float2 pd = *(const float2*)&Ls[(rb + g + 8) * LSTR + kb + 8];
                uint32_t a0h, a0l, a1h, a1l, a2h, a2l, a3h, a3l;
                split2(pa.x, pa.y, a0h, a0l);
                split2(pc.x, pc.y, a1h, a1l);
                split2(pb.x, pb.y, a2h, a2l);
                split2(pd.x, pd.y, a3h, a3l);
                mma_bf16(oacc[rt], a0h, a1h, a2h, a3h, bh0, bh1);
                mma_bf16(oacc[rt], a0h, a1h, a2h, a3h, bl0, bl1);
                mma_bf16(oacc[rt], a0l, a1l, a2l, a3l, bh0, bh1);
            }
        }
        __syncthreads();
    }

    // ---- epilogue ----
    {
        int d0 = wid * 8 + 2 * l3;
        #pragma unroll
        for (int rt = 0; rt < 2; rt++) {
            int ra = rt * 16 + g, rb = ra + 8;
            float tw0 = tailw[ra], tw1 = tailw[rb];
            const float* vt0 = Vt + ((size_t)h * T_ + t0 + ra) * 64;
            const float* vt1 = Vt + ((size_t)h * T_ + t0 + rb) * 64;
            float* o0 = attout + (size_t)(t0 + ra) * C_ + h * 64 + d0;
            float* o1 = attout + (size_t)(t0 + rb) * C_ + h * 64 + d0;
            o0[0] = oacc[rt][0] + tw0 * vt0[d0];
            o0[1] = oacc[rt][1] + tw0 * vt0[d0 + 1];
            o1[0] = oacc[rt][2] + tw1 * vt1[d0];
            o1[1] = oacc[rt][3] + tw1 * vt1[d0 + 1];
        }
    }
}

extern "C" void kernel_launch(void* const* d_in, const int* in_sizes, int n_in,
                              void* d_out, int out_size) {
    const float* x   = (const float*)d_in[0];
    const float* Wq  = (const float*)d_in[1];
    const float* Wk  = (const float*)d_in[2];
    const float* Wv  = (const float*)d_in[3];
    const float* Wks = (const float*)d_in[4];
    const float* bks = (const float*)d_in[5];
    const float* Wvs = (const float*)d_in[6];
    const float* bvs = (const float*)d_in[7];
    const float* Wc  = (const float*)d_in[8];
    const float* bc  = (const float*)d_in[9];
    float* out = (float*)d_out;

    void *pq, *pk, *pv, *pG, *pWfh, *pWfl;
    void *pWqh, *pWql, *pWkh, *pWkl, *pWvh, *pWvl, *pWch, *pWcl;
    void *pKt, *pVt, *pKs, *pVs, *pKph, *pKpl, *pVph, *pVpl, *pCT, *pAtt;
    cudaGetSymbolAddress(&pq, g_q);     cudaGetSymbolAddress(&pk, g_k);
    cudaGetSymbolAddress(&pv, g_v);     cudaGetSymbolAddress(&pG, g_G);
    cudaGetSymbolAddress(&pWfh, g_Wfh); cudaGetSymbolAddress(&pWfl, g_Wfl);
    cudaGetSymbolAddress(&pWqh, g_Wqh); cudaGetSymbolAddress(&pWql, g_Wql);
    cudaGetSymbolAddress(&pWkh, g_Wkh); cudaGetSymbolAddress(&pWkl, g_Wkl);
    cudaGetSymbolAddress(&pWvh, g_Wvh); cudaGetSymbolAddress(&pWvl, g_Wvl);
    cudaGetSymbolAddress(&pWch, g_Wch); cudaGetSymbolAddress(&pWcl, g_Wcl);
    cudaGetSymbolAddress(&pKt, g_Kt);   cudaGetSymbolAddress(&pVt, g_Vt);
    cudaGetSymbolAddress(&pKs, g_Ks);   cudaGetSymbolAddress(&pVs, g_Vs);
    cudaGetSymbolAddress(&pKph, g_Kph); cudaGetSymbolAddress(&pKpl, g_Kpl);
    cudaGetSymbolAddress(&pVph, g_Vph); cudaGetSymbolAddress(&pVpl, g_Vpl);
    cudaGetSymbolAddress(&pCT, g_CT);   cudaGetSymbolAddress(&pAtt, g_att);

    cudaFuncSetAttribute(gemm_tc<0,1>, cudaFuncAttributeMaxDynamicSharedMemorySize, GT_SMEM);
    cudaFuncSetAttribute(gemm_qkv,     cudaFuncAttributeMaxDynamicSharedMemorySize, GT_SMEM);
    cudaFuncSetAttribute(gproj_mma,    cudaFuncAttributeMaxDynamicSharedMemorySize, GP_SMEM);
    cudaFuncSetAttribute(attn_mma,     cudaFuncAttributeMaxDynamicSharedMemorySize, AT_SMEM);

    split_wf<<<(2048*128)/256, 256>>>(Wks, Wvs, (uint32_t*)pWfh, (uint32_t*)pWfl);
    split_w4<<<dim3((384*C_ + 255)/256, 4), 256>>>(Wq, Wk, Wv, Wc,
        (uint32_t*)pWqh, (uint32_t*)pWql, (uint32_t*)pWkh, (uint32_t*)pWkl,
        (uint32_t*)pWvh, (uint32_t*)pWvl, (uint32_t*)pWch, (uint32_t*)pWcl);

    gemm_qkv<<<dim3(18, T_/128), 256, GT_SMEM>>>(x,
        (const uint32_t*)pWqh, (const uint32_t*)pWql,
        (const uint32_t*)pWkh, (const uint32_t*)pWkl,
        (const uint32_t*)pWvh, (const uint32_t*)pWvl,
        (float*)pq, (float*)pk, (float*)pv);

    gproj_mma<<<dim3(R_/128, 2), 256, GP_SMEM>>>((const float*)pk, (const float*)pv,
                                                 (const uint32_t*)pWfh, (const uint32_t*)pWfl,
                                                 (float*)pG);

    scan_kernel<<<dim3(8, NH_, 2), 64>>>((const float*)pG, bks, bvs,
        (float*)pKt, (float*)pVt, (float*)pKs, (float*)pVs, (float*)pCT);
    hilevel_kernel<<<dim3(NH_, 2), 64>>>((const float*)pCT, bks, bvs,
        (float*)pKs, (float*)pVs);

    pack_kv<<<dim3((NH_*1024*32)/256, 2), 256>>>((const float*)pKs, (const float*)pVs,
        (uint32_t*)pKph, (uint32_t*)pKpl, (uint32_t*)pVph, (uint32_t*)pVpl);

    attn_mma<<<dim3(T_/32, NH_), 256, AT_SMEM>>>((const float*)pq,
        (const uint32_t*)pKph, (const uint32_t*)pKpl,
        (const uint32_t*)pVph, (const uint32_t*)pVpl,
        (const float*)pKt, (const float*)pVt, (float*)pAtt);

    gemm_tc<0,1><<<dim3(C_/128, T_/128), 256, GT_SMEM>>>((const float*)pAtt,
        (const uint32_t*)pWch, (const uint32_t*)pWcl, bc, out, T_, C_, C_);
}

// round 17
// speedup vs baseline: 1.0443x; 1.0443x over previous
#include <cuda_runtime.h>
#include <math.h>
#include <stdint.h>

#define T_  2048
#define C_  768
#define NH_ 12
#define HS_ 64
#define S_  1023
#define R_  (T_*NH_)
#define SCALE_ 0.125f

// ---------------- scratch ----------------
__device__ float g_q [T_*C_];
__device__ float g_k [T_*C_];
__device__ float g_v [T_*C_];
__device__ float g_G [(size_t)2*R_*128];   // two K-split partials
__device__ uint32_t g_Wfh[(size_t)2048*128];
__device__ uint32_t g_Wfl[(size_t)2048*128];
__device__ uint32_t g_Wqh[384*C_], g_Wql[384*C_];
__device__ uint32_t g_Wkh[384*C_], g_Wkl[384*C_];
__device__ uint32_t g_Wvh[384*C_], g_Wvl[384*C_];
__device__ uint32_t g_Wch[384*C_], g_Wcl[384*C_];
__device__ float g_Kt[(size_t)NH_*T_*HS_];
__device__ float g_Vt[(size_t)NH_*T_*HS_];
__device__ float g_Ks[(size_t)NH_*S_*HS_];
__device__ float g_Vs[(size_t)NH_*S_*HS_];
__device__ uint32_t g_Kph[(size_t)NH_*1024*32];
__device__ uint32_t g_Kpl[(size_t)NH_*1024*32];
__device__ uint32_t g_Vph[(size_t)NH_*512*64];
__device__ uint32_t g_Vpl[(size_t)NH_*512*64];
__device__ float g_CT[2*NH_*8*HS_];
__device__ float g_att[T_*C_];

// ---------------- helpers ----------------
__device__ __forceinline__ uint32_t smem_u32(const void* p) {
    uint32_t a;
    asm("{ .reg .u64 t; cvta.to.shared.u64 t, %1; cvt.u32.u64 %0, t; }" : "=r"(a) : "l"(p));
    return a;
}
__device__ __forceinline__ uint32_t pk_bf2(float x0, float x1) {
    uint32_t r;
    asm("cvt.rn.bf16x2.f32 %0, %1, %2;" : "=r"(r) : "f"(x1), "f"(x0));
    return r;
}
__device__ __forceinline__ void split2(float x0, float x1, uint32_t& hi, uint32_t& lo) {
    hi = pk_bf2(x0, x1);
    float h0 = __uint_as_float(hi << 16);
    float h1 = __uint_as_float(hi & 0xFFFF0000u);
    lo = pk_bf2(x0 - h0, x1 - h1);
}
__device__ __forceinline__ void cp_async16(uint32_t dst, const void* src) {
    asm volatile("cp.async.ca.shared.global [%0], [%1], 16;" :: "r"(dst), "l"(src) : "memory");
}
#define CP_COMMIT() asm volatile("cp.async.commit_group;" ::: "memory")
#define CP_WAIT1()  asm volatile("cp.async.wait_group 1;" ::: "memory")
#define CP_WAIT0()  asm volatile("cp.async.wait_group 0;" ::: "memory")

__device__ __forceinline__ void mma_bf16(float* c, uint32_t a0, uint32_t a1,
                                         uint32_t a2, uint32_t a3,
                                         uint32_t b0, uint32_t b1) {
    asm volatile(
        "mma.sync.aligned.m16n8k16.row.col.f32.bf16.bf16.f32 "
        "{%0,%1,%2,%3}, {%4,%5,%6,%7}, {%8,%9}, {%0,%1,%2,%3};"
        : "+f"(c[0]), "+f"(c[1]), "+f"(c[2]), "+f"(c[3])
        : "r"(a0), "r"(a1), "r"(a2), "r"(a3), "r"(b0), "r"(b1));
}

// ---------------- prep kernels ----------------
__global__ void split_w4(const float* __restrict__ Wq, const float* __restrict__ Wk,
                         const float* __restrict__ Wv, const float* __restrict__ Wc,
                         uint32_t* __restrict__ Wqh, uint32_t* __restrict__ Wql,
                         uint32_t* __restrict__ Wkh, uint32_t* __restrict__ Wkl,
                         uint32_t* __restrict__ Wvh, uint32_t* __restrict__ Wvl,
                         uint32_t* __restrict__ Wch, uint32_t* __restrict__ Wcl) {
    int i = blockIdx.x * 256 + threadIdx.x;
    if (i >= 384 * C_) return;
    int sel = blockIdx.y;
    const float* W = (sel == 0) ? Wq : (sel == 1) ? Wk : (sel == 2) ? Wv : Wc;
    uint32_t* Whi = (sel == 0) ? Wqh : (sel == 1) ? Wkh : (sel == 2) ? Wvh : Wch;
    uint32_t* Wlo = (sel == 0) ? Wql : (sel == 1) ? Wkl : (sel == 2) ? Wvl : Wcl;
    int kr = i / C_, n = i - kr * C_;
    float x0 = W[(size_t)(2 * kr) * C_ + n];
    float x1 = W[(size_t)(2 * kr + 1) * C_ + n];
    uint32_t hi, lo; split2(x0, x1, hi, lo);
    Whi[i] = hi; Wlo[i] = lo;
}
__global__ void split_wf(const float* __restrict__ Wks, const float* __restrict__ Wvs,
                         uint32_t* __restrict__ Whi, uint32_t* __restrict__ Wlo) {
    int i = blockIdx.x * 256 + threadIdx.x;
    int kr = i >> 7, n = i & 127;
    int r0 = 2 * kr, r1 = 2 * kr + 1;
    float x0 = (n < 64) ? Wks[(size_t)r0 * 64 + n] : Wvs[(size_t)r0 * 64 + (n - 64)];
    float x1 = (n < 64) ? Wks[(size_t)r1 * 64 + n] : Wvs[(size_t)r1 * 64 + (n - 64)];
    uint32_t hi, lo; split2(x0, x1, hi, lo);
    Whi[i] = hi; Wlo[i] = lo;
}
__global__ void pack_kv(const float* __restrict__ Ks, const float* __restrict__ Vs,
                        uint32_t* __restrict__ Kph, uint32_t* __restrict__ Kpl,
                        uint32_t* __restrict__ Vph, uint32_t* __restrict__ Vpl) {
    int i = blockIdx.x * 256 + threadIdx.x;
    int h = i >> 15, rem = i & 32767;
    float x0, x1;
    if (blockIdx.y == 0) {
        int s = rem >> 5, dpr = rem & 31;
        x0 = 0.f; x1 = 0.f;
        if (s < S_) {
            const float* p = Ks + ((size_t)h * S_ + s) * 64 + 2 * dpr;
            x0 = p[0]; x1 = p[1];
        }
        uint32_t hi, lo; split2(x0, x1, hi, lo);
        Kph[i] = hi; Kpl[i] = lo;
    } else {
        int sr = rem >> 6, d = rem & 63;
        int s0 = 2 * sr, s1 = 2 * sr + 1;
        x0 = (s0 < S_) ? Vs[((size_t)h * S_ + s0) * 64 + d] : 0.f;
        x1 = (s1 < S_) ? Vs[((size_t)h * S_ + s1) * 64 + d] : 0.f;
        uint32_t hi, lo; split2(x0, x1, hi, lo);
        Vph[i] = hi; Vpl[i] = lo;
    }
}

// ---------------- generic bf16-split GEMM ----------------
#define GT_A0 0
#define GT_A1 34816
#define GT_B0 69632
#define GT_B1 104448
#define GT_SMEM 139264

template<int ACT, int BIAS>
__global__ __launch_bounds__(256)
void gemm_tc(const float* __restrict__ A, const uint32_t* __restrict__ Bhi,
             const uint32_t* __restrict__ Blo, const float* __restrict__ bias,
             float* __restrict__ C, int M, int N, int K)
{
    extern __shared__ char smem[];
    const uint32_t sb = smem_u32(smem);
    const int tid = threadIdx.x;
    const int wid = tid >> 5, lane = tid & 31;
    const int g = lane >> 2, l3 = lane & 3;
    const int bm = blockIdx.y * 128, bn = blockIdx.x * 128;
    const int r0 = wid * 16 + g, r1 = r0 + 8;
    const int nch = K >> 6;

    float acc[16][4];
    #pragma unroll
    for (int nt = 0; nt < 16; nt++)
        #pragma unroll
        for (int c = 0; c < 4; c++) acc[nt][c] = 0.f;

    auto stage = [&](int c, int buf) {
        uint32_t aB = sb + (buf ? GT_A1 : GT_A0);
        uint32_t bB = sb + (buf ? GT_B1 : GT_B0);
        #pragma unroll
        for (int m = 0; m < 8; m++) {
            int idx = tid + m * 256;
            int r = idx >> 4, q = idx & 15;
            cp_async16(aB + r * 272 + q * 16,
                       A + (size_t)(bm + r) * K + c * 64 + q * 4);
        }
        #pragma unroll
        for (int m = 0; m < 4; m++) {
            int f = tid + m * 256;
            int kr = f >> 5, q = f & 31;
            cp_async16(bB + kr * 544 + q * 16,
                       Bhi + (size_t)(c * 32 + kr) * N + bn + q * 4);
            cp_async16(bB + 17408 + kr * 544 + q * 16,
                       Blo + (size_t)(c * 32 + kr) * N + bn + q * 4);
        }
    };

    stage(0, 0); CP_COMMIT();

    for (int i = 0; i < nch; i++) {
        int buf = i & 1;
        if (i + 1 < nch) { stage(i + 1, buf ^ 1); CP_COMMIT(); CP_WAIT1(); }
        else CP_WAIT0();
        __syncthreads();
        const float* Ab = (const float*)(smem + (buf ? GT_A1 : GT_A0));
        const uint32_t* Bh = (const uint32_t*)(smem + (buf ? GT_B1 : GT_B0));
        const uint32_t* Bl = Bh + 17408 / 4;
        #pragma unroll
        for (int kk = 0; kk < 4; kk++) {
            int kb = kk * 16 + 2 * l3;
            float2 xa = *(const float2*)&Ab[r0 * 68 + kb];
            float2 xb = *(const float2*)&Ab[r0 * 68 + kb + 8];
            float2 xc = *(const float2*)&Ab[r1 * 68 + kb];
            float2 xd = *(const float2*)&Ab[r1 * 68 + kb + 8];
            uint32_t a0h, a0l, a1h, a1l, a2h, a2l, a3h, a3l;
            split2(xa.x, xa.y, a0h, a0l);
            split2(xc.x, xc.y, a1h, a1l);
            split2(xb.x, xb.y, a2h, a2l);
            split2(xd.x, xd.y, a3h, a3l);
            const uint32_t* bh0 = Bh + (kk * 8 + l3) * 136 + g;
            const uint32_t* bl0 = Bl + (kk * 8 + l3) * 136 + g;
            #pragma unroll
            for (int nt = 0; nt < 16; nt++) {
                uint32_t bh_0 = bh0[nt * 8], bh_1 = bh0[4 * 136 + nt * 8];
                uint32_t bl_0 = bl0[nt * 8], bl_1 = bl0[4 * 136 + nt * 8];
                mma_bf16(acc[nt], a0h, a1h, a2h, a3h, bh_0, bh_1);
                mma_bf16(acc[nt], a0h, a1h, a2h, a3h, bl_0, bl_1);
                mma_bf16(acc[nt], a0l, a1l, a2l, a3l, bh_0, bh_1);
            }
        }
        __syncthreads();
    }

    #pragma unroll
    for (int nt = 0; nt < 16; nt++) {
        int col = bn + nt * 8 + 2 * l3;
        float z0 = acc[nt][0], z1 = acc[nt][1], z2 = acc[nt][2], z3 = acc[nt][3];
        if (BIAS) { z0 += bias[col]; z1 += bias[col + 1]; z2 += bias[col]; z3 += bias[col + 1]; }
        if (ACT) {
            z0 = (z0 > 0.f) ? (z0 + 1.f) : expf(z0);
            z1 = (z1 > 0.f) ? (z1 + 1.f) : expf(z1);
            z2 = (z2 > 0.f) ? (z2 + 1.f) : expf(z2);
            z3 = (z3 > 0.f) ? (z3 + 1.f) : expf(z3);
        }
        *(float2*)(C + (size_t)(bm + r0) * N + col) = make_float2(z0, z1);
        *(float2*)(C + (size_t)(bm + r1) * N + col) = make_float2(z2, z3);
    }
}

// ---------------- fused QKV GEMM ----------------
__global__ __launch_bounds__(256)
void gemm_qkv(const float* __restrict__ A,
              const uint32_t* __restrict__ Bh0, const uint32_t* __restrict__ Bl0,
              const uint32_t* __restrict__ Bh1, const uint32_t* __restrict__ Bl1,
              const uint32_t* __restrict__ Bh2, const uint32_t* __restrict__ Bl2,
              float* __restrict__ C0, float* __restrict__ C1, float* __restrict__ C2)
{
    extern __shared__ char smem[];
    const uint32_t sb = smem_u32(smem);
    const int tid = threadIdx.x;
    const int wid = tid >> 5, lane = tid & 31;
    const int g = lane >> 2, l3 = lane & 3;
    const int sel = blockIdx.x / 6;
    const uint32_t* Bhi = (sel == 0) ? Bh0 : (sel == 1) ? Bh1 : Bh2;
    const uint32_t* Blo = (sel == 0) ? Bl0 : (sel == 1) ? Bl1 : Bl2;
    float* C = (sel == 0) ? C0 : (sel == 1) ? C1 : C2;
    const bool act = sel < 2;
    const int bm = blockIdx.y * 128, bn = (blockIdx.x % 6) * 128;
    const int r0 = wid * 16 + g, r1 = r0 + 8;
    const int N = C_, K = C_, nch = K >> 6;

    float acc[16][4];
    #pragma unroll
    for (int nt = 0; nt < 16; nt++)
        #pragma unroll
        for (int c = 0; c < 4; c++) acc[nt][c] = 0.f;

    auto stage = [&](int c, int buf) {
        uint32_t aB = sb + (buf ? GT_A1 : GT_A0);
        uint32_t bB = sb + (buf ? GT_B1 : GT_B0);
        #pragma unroll
        for (int m = 0; m < 8; m++) {
            int idx = tid + m * 256;
            int r = idx >> 4, q = idx & 15;
            cp_async16(aB + r * 272 + q * 16,
                       A + (size_t)(bm + r) * K + c * 64 + q * 4);
        }
        #pragma unroll
        for (int m = 0; m < 4; m++) {
            int f = tid + m * 256;
            int kr = f >> 5, q = f & 31;
            cp_async16(bB + kr * 544 + q * 16,
                       Bhi + (size_t)(c * 32 + kr) * N + bn + q * 4);
            cp_async16(bB + 17408 + kr * 544 + q * 16,
                       Blo + (size_t)(c * 32 + kr) * N + bn + q * 4);
        }
    };

    stage(0, 0); CP_COMMIT();

    for (int i = 0; i < nch; i++) {
        int buf = i & 1;
        if (i + 1 < nch) { stage(i + 1, buf ^ 1); CP_COMMIT(); CP_WAIT1(); }
        else CP_WAIT0();
        __syncthreads();
        const float* Ab = (const float*)(smem + (buf ? GT_A1 : GT_A0));
        const uint32_t* Bh = (const uint32_t*)(smem + (buf ? GT_B1 : GT_B0));
        const uint32_t* Bl = Bh + 17408 / 4;
        #pragma unroll
        for (int kk = 0; kk < 4; kk++) {
            int kb = kk * 16 + 2 * l3;
            float2 xa = *(const float2*)&Ab[r0 * 68 + kb];
            float2 xb = *(const float2*)&Ab[r0 * 68 + kb + 8];
            float2 xc = *(const float2*)&Ab[r1 * 68 + kb];
            float2 xd = *(const float2*)&Ab[r1 * 68 + kb + 8];
            uint32_t a0h, a0l, a1h, a1l, a2h, a2l, a3h, a3l;
            split2(xa.x, xa.y, a0h, a0l);
            split2(xc.x, xc.y, a1h, a1l);
            split2(xb.x, xb.y, a2h, a2l);
            split2(xd.x, xd.y, a3h, a3l);
            const uint32_t* bh0 = Bh + (kk * 8 + l3) * 136 + g;
            const uint32_t* bl0 = Bl + (kk * 8 + l3) * 136 + g;
            #pragma unroll
            for (int nt = 0; nt < 16; nt++) {
                uint32_t bh_0 = bh0[nt * 8], bh_1 = bh0[4 * 136 + nt * 8];
                uint32_t bl_0 = bl0[nt * 8], bl_1 = bl0[4 * 136 + nt * 8];
                mma_bf16(acc[nt], a0h, a1h, a2h, a3h, bh_0, bh_1);
                mma_bf16(acc[nt], a0h, a1h, a2h, a3h, bl_0, bl_1);
                mma_bf16(acc[nt], a0l, a1l, a2l, a3l, bh_0, bh_1);
            }
        }
        __syncthreads();
    }

    #pragma unroll
    for (int nt = 0; nt < 16; nt++) {
        int col = bn + nt * 8 + 2 * l3;
        float z0 = acc[nt][0], z1 = acc[nt][1], z2 = acc[nt][2], z3 = acc[nt][3];
        if (act) {
            z0 = (z0 > 0.f) ? (z0 + 1.f) : expf(z0);
            z1 = (z1 > 0.f) ? (z1 + 1.f) : expf(z1);
            z2 = (z2 > 0.f) ? (z2 + 1.f) : expf(z2);
            z3 = (z3 > 0.f) ? (z3 + 1.f) : expf(z3);
        }
        *(float2*)(C + (size_t)(bm + r0) * N + col) = make_float2(z0, z1);
        *(float2*)(C + (size_t)(bm + r1) * N + col) = make_float2(z2, z3);
    }
}

// ---------------- gproj: R10 proven shape, K-split x2 ----------------
#define GP_K0 0
#define GP_B0 34816
#define GP_B1 69632
#define GP_SMEM 104448

__global__ __launch_bounds__(256)
void gproj_mma(const float* __restrict__ kmat, const float* __restrict__ vmat,
               const uint32_t* __restrict__ Wfh, const uint32_t* __restrict__ Wfl,
               float* __restrict__ G)
{
    extern __shared__ char smem[];
    const uint32_t sb = smem_u32(smem);
    const int tid = threadIdx.x;
    const int wid = tid >> 5, lane = tid & 31;
    const int g = lane >> 2, l3 = lane & 3;
    const int rbase = blockIdx.x * 128;
    const int cbase = blockIdx.y * 32;
    float* Gout = G + (size_t)blockIdx.y * R_ * 128;
    const int r0 = wid * 16 + g, r1 = r0 + 8;

    auto stageB = [&](int c, int buf) {
        uint32_t bB = sb + (buf ? GP_B1 : GP_B0);
        #pragma unroll
        for (int m = 0; m < 4; m++) {
            int f = tid + m * 256;
            int kr = f >> 5, q = f & 31;
            cp_async16(bB + kr * 544 + q * 16,
                       Wfh + (size_t)((cbase + c) * 32 + kr) * 128 + q * 4);
            cp_async16(bB + 17408 + kr * 544 + q * 16,
                       Wfl + (size_t)((cbase + c) * 32 + kr) * 128 + q * 4);
        }
    };

    #pragma unroll
    for (int m = 0; m < 8; m++) {
        int idx = tid + m * 256;
        int r = idx >> 4, q = idx & 15;
        cp_async16(sb + GP_K0 + r * 272 + q * 16,
                   kmat + (size_t)(rbase + r) * 64 + q * 4);
    }
    stageB(0, 0); CP_COMMIT();

    float2 v0a[4], v0b[4], v1a[4], v1b[4];
    {
        const float* vp0 = vmat + (size_t)(rbase + r0) * 64;
        const float* vp1 = vmat + (size_t)(rbase + r1) * 64;
        #pragma unroll
        for (int kk = 0; kk < 4; kk++) {
            v0a[kk] = *(const float2*)(vp0 + kk * 16 + 2 * l3);
            v0b[kk] = *(const float2*)(vp0 + kk * 16 + 2 * l3 + 8);
            v1a[kk] = *(const float2*)(vp1 + kk * 16 + 2 * l3);
            v1b[kk] = *(const float2*)(vp1 + kk * 16 + 2 * l3 + 8);
        }
    }

    float acc[16][4];
    #pragma unroll
    for (int nt = 0; nt < 16; nt++)
        #pragma unroll
        for (int c = 0; c < 4; c++) acc[nt][c] = 0.f;

    const float* Ksm = (const float*)(smem + GP_K0);

    for (int i = 0; i < 32; i++) {
        int buf = i & 1;
        if (i < 31) { stageB(i + 1, buf ^ 1); CP_COMMIT(); CP_WAIT1(); }
        else CP_WAIT0();
        __syncthreads();
        const uint32_t* Bh = (const uint32_t*)(smem + (buf ? GP_B1 : GP_B0));
        const uint32_t* Bl = Bh + 17408 / 4;
        float k0 = Ksm[r0 * 68 + cbase + i];
        float k1 = Ksm[r1 * 68 + cbase + i];
        #pragma unroll
        for (int kk = 0; kk < 4; kk++) {
            uint32_t a0h, a0l, a1h, a1l, a2h, a2l, a3h, a3l;
            split2(k0 * v0a[kk].x, k0 * v0a[kk].y, a0h, a0l);
            split2(k1 * v1a[kk].x, k1 * v1a[kk].y, a1h, a1l);
            split2(k0 * v0b[kk].x, k0 * v0b[kk].y, a2h, a2l);
            split2(k1 * v1b[kk].x, k1 * v1b[kk].y, a3h, a3l);
            const uint32_t* bh0 = Bh + (kk * 8 + l3) * 136 + g;
            const uint32_t* bl0 = Bl + (kk * 8 + l3) * 136 + g;
            #pragma unroll
            for (int nt = 0; nt < 16; nt++) {
                uint32_t bh_0 = bh0[nt * 8], bh_1 = bh0[4 * 136 + nt * 8];
                uint32_t bl_0 = bl0[nt * 8], bl_1 = bl0[4 * 136 + nt * 8];
                mma_bf16(acc[nt], a0h, a1h, a2h, a3h, bh_0, bh_1);
                mma_bf16(acc[nt], a0h, a1h, a2h, a3h, bl_0, bl_1);
                mma_bf16(acc[nt], a0l, a1l, a2l, a3l, bh_0, bh_1);
            }
        }
        __syncthreads();
    }

    #pragma unroll
    for (int nt = 0; nt < 16; nt++) {
        int col = nt * 8 + 2 * l3;
        *(float2*)(Gout + (size_t)(rbase + r0) * 128 + col) = make_float2(acc[nt][0], acc[nt][1]);
        *(float2*)(Gout + (size_t)(rbase + r1) * 128 + col) = make_float2(acc[nt][2], acc[nt][3]);
    }
}

// ------- scan (sums two K-split partials) + hilevel -------
__global__ __launch_bounds__(64)
void scan_kernel(const float* __restrict__ G,
                 const float* __restrict__ bks, const float* __restrict__ bvs,
                 float* __restrict__ Kt, float* __restrict__ Vt,
                 float* __restrict__ Ksg, float* __restrict__ Vsg,
                 float* __restrict__ CT)
{
    const int d = threadIdx.x;
    const int chunk = blockIdx.x;
    const int h = blockIdx.y;
    const int map = blockIdx.z;
    const float bias = map ? bvs[d] : bks[d];
    float* tailp = map ? Vt : Kt;
    float* setp  = map ? Vsg : Ksg;
    const size_t HALF = (size_t)R_ * 128;

    float acc = 0.f, prev4 = 0.f;
    float prevl[7];
    #pragma unroll
    for (int i = 0; i < 7; i++) prevl[i] = 0.f;

    const int t0 = chunk * 256;
    for (int tb = 0; tb < 256; tb += 8) {
        float xv[8];
        #pragma unroll
        for (int i = 0; i < 8; i++) {
            size_t o = ((size_t)((t0 + tb + i) * NH_ + h)) * 128 + map * 64 + d;
            xv[i] = G[o] + G[o + HALF];
        }
        #pragma unroll
        for (int i = 0; i < 8; i++) {
            const int t = t0 + tb + i;
            acc += xv[i];
            tailp[((size_t)h * T_ + t) * 64 + d] = acc - prev4 + bias;
            const int tp1 = t + 1;
            if ((tp1 & 3) == 0) prev4 = acc;
            #pragma unroll
            for (int li = 0; li < 7; li++) {
                const int l = li + 2;
                if ((tp1 & ((1 << l) - 1)) == 0) {
                    const int offl = 1024 - (4096 >> l);
                    const int gb = (tp1 >> l) - 1;
                    setp[((size_t)h * S_ + offl + gb) * 64 + d] = acc - prevl[li] + bias;
                    prevl[li] = acc;
                }
            }
        }
    }
    CT[((size_t)(map * NH_ + h) * 8 + chunk) * 64 + d] = acc;
}

__global__ __launch_bounds__(64)
void hilevel_kernel(const float* __restrict__ CT,
                    const float* __restrict__ bks, const float* __restrict__ bvs,
                    float* __restrict__ Ksg, float* __restrict__ Vsg)
{
    const int d = threadIdx.x;
    const int h = blockIdx.x;
    const int map = blockIdx.y;
    const float bias = map ? bvs[d] : bks[d];
    float* setp = map ? Vsg : Ksg;
    const float* ct = CT + ((size_t)(map * NH_ + h) * 8) * 64 + d;
    float c[8];
    #pragma unroll
    for (int i = 0; i < 8; i++) c[i] = ct[i * 64];
    #pragma unroll
    for (int b = 0; b < 4; b++)
        setp[((size_t)h * S_ + 1016 + b) * 64 + d] = c[2*b] + c[2*b+1] + bias;
    #pragma unroll
    for (int b = 0; b < 2; b++)
        setp[((size_t)h * S_ + 1020 + b) * 64 + d] =
            c[4*b] + c[4*b+1] + c[4*b+2] + c[4*b+3] + bias;
    setp[((size_t)h * S_ + 1022) * 64 + d] =
        c[0]+c[1]+c[2]+c[3]+c[4]+c[5]+c[6]+c[7] + bias;
}

// ---------------- attention: R14 body + heavy-first scheduling only ----------------
#define AT_QS   0
#define AT_ENDS 8192
#define AT_TW   12288
#define AT_LS   12416
#define AT_BUF  143744
#define AT_BSTR 36864
#define AT_SMEM 217472
#define LSTR 1026

__global__ __launch_bounds__(256)
void attn_mma(const float* __restrict__ q,
              const uint32_t* __restrict__ Kph, const uint32_t* __restrict__ Kpl,
              const uint32_t* __restrict__ Vph, const uint32_t* __restrict__ Vpl,
              const float* __restrict__ Kt, const float* __restrict__ Vt,
              float* __restrict__ attout)
{
    extern __shared__ char smem[];
    const uint32_t sb = smem_u32(smem);
    float* Qs = (float*)(smem + AT_QS);
    int* endsI = (int*)(smem + AT_ENDS);
    float* tailw = (float*)(smem + AT_TW);
    float* Ls = (float*)(smem + AT_LS);

    const int h = blockIdx.y;
    // heavy blocks (large t0, more active chunks) scheduled first
    const int t0 = ((int)gridDim.x - 1 - (int)blockIdx.x) * 32;
    const int tid = threadIdx.x;
    const int wid = tid >> 5, lane = tid & 31;
    const int g = lane >> 2, l3 = lane & 3;

    // active-chunk list: chunk c is fully masked when its minimum set-end
    // exceeds t0+32.  min ends per chunk: {4, 516, 1028, 1540, 8, 1032, 16, 32}
    const int tmax = t0 + 32;
    int cl[8];
    int nc = 0;
    {
        const int minend[8] = {4, 516, 1028, 1540, 8, 1032, 16, 32};
        #pragma unroll
        for (int c = 0; c < 8; c++)
            if (minend[c] <= tmax) cl[nc++] = c;
    }

    #pragma unroll
    for (int it = 0; it < 8; it++) {
        int idx = tid + it * 256;
        Qs[idx] = q[(size_t)(t0 + (idx >> 6)) * C_ + h * 64 + (idx & 63)];
    }
    for (int s = tid; s < 1024; s += 256) {
        if (s < S_) {
            int off = 0, n = 512, l = 2;
            while (s >= off + n) { off += n; n >>= 1; l++; }
            endsI[s] = (s - off + 1) << l;
        } else endsI[s] = 0x7fffffff;
    }
    // fill logits of fully-masked chunks with -1e30 (identical to masked path)
    {
        const int minend[8] = {4, 516, 1028, 1540, 8, 1032, 16, 32};
        for (int c = 0; c < 8; c++) {
            if (minend[c] > tmax) {
                for (int idx = tid; idx < 32 * 128; idx += 256) {
                    int row = idx >> 7, sloc = idx & 127;
                    Ls[row * LSTR + c * 128 + sloc] = -1e30f;
                }
            }
        }
    }

    auto stageK = [&](int c, int buf) {
        uint32_t base = sb + AT_BUF + buf * AT_BSTR;
        #pragma unroll
        for (int m = 0; m < 4; m++) {
            int idx = tid + m * 256;
            int row = idx >> 3, q16 = idx & 7;
            size_t gro = ((size_t)h * 1024 + c * 128 + row) * 32 + q16 * 4;
            cp_async16(base + row * 144 + q16 * 16, Kph + gro);
            cp_async16(base + 18432 + row * 144 + q16 * 16, Kpl + gro);
        }
    };
    auto stageV = [&](int c, int buf) {
        uint32_t base = sb + AT_BUF + buf * AT_BSTR;
        #pragma unroll
        for (int m = 0; m < 4; m++) {
            int idx = tid + m * 256;
            int row = idx >> 4, q16 = idx & 15;
            size_t gro = ((size_t)h * 512 + c * 64 + row) * 64 + q16 * 4;
            cp_async16(base + row * 288 + q16 * 16, Vph + gro);
            cp_async16(base + 18432 + row * 288 + q16 * 16, Vpl + gro);
        }
    };

    stageK(cl[0], 0); CP_COMMIT();
    __syncthreads();

    uint32_t qa_h[2][4][4], qa_l[2][4][4];
    #pragma unroll
    for (int rt = 0; rt < 2; rt++) {
        int rb = rt * 16;
        #pragma unroll
        for (int kk = 0; kk < 4; kk++) {
            int kb = kk * 16 + 2 * l3;
            float2 xa = *(const float2*)&Qs[(rb + g) * 64 + kb];
            float2 xb = *(const float2*)&Qs[(rb + g) * 64 + kb + 8];
            float2 xc = *(const float2*)&Qs[(rb + g + 8) * 64 + kb];
            float2 xd = *(const float2*)&Qs[(rb + g + 8) * 64 + kb + 8];
            split2(xa.x, xa.y, qa_h[rt][kk][0], qa_l[rt][kk][0]);
            split2(xc.x, xc.y, qa_h[rt][kk][1], qa_l[rt][kk][1]);
            split2(xb.x, xb.y, qa_h[rt][kk][2], qa_l[rt][kk][2]);
            split2(xd.x, xd.y, qa_h[rt][kk][3], qa_l[rt][kk][3]);
        }
    }

    // ---- logits over active chunks ----
    for (int ci = 0; ci < nc; ci++) {
        int c = cl[ci];
        int buf = ci & 1;
        if (ci + 1 < nc) { stageK(cl[ci + 1], buf ^ 1); CP_COMMIT(); CP_WAIT1(); }
        else CP_WAIT0();
        __syncthreads();
        const uint32_t* Kh = (const uint32_t*)(smem + AT_BUF + buf * AT_BSTR);
        const uint32_t* Kl = Kh + 18432 / 4;
        #pragma unroll
        for (int nt2 = 0; nt2 < 2; nt2++) {
            int nt = wid * 2 + nt2;
            float acc4[2][4] = {{0.f,0.f,0.f,0.f},{0.f,0.f,0.f,0.f}};
            #pragma unroll
            for (int kk = 0; kk < 4; kk++) {
                const uint32_t* kr = Kh + (nt * 8 + g) * 36 + kk * 8 + l3;
                const uint32_t* krl = Kl + (nt * 8 + g) * 36 + kk * 8 + l3;
                uint32_t bh0 = kr[0], bh1 = kr[4];
                uint32_t bl0 = krl[0], bl1 = krl[4];
                #pragma unroll
                for (int rt = 0; rt < 2; rt++) {
                    mma_bf16(acc4[rt], qa_h[rt][kk][0], qa_h[rt][kk][1], qa_h[rt][kk][2], qa_h[rt][kk][3], bh0, bh1);
                    mma_bf16(acc4[rt], qa_h[rt][kk][0], qa_h[rt][kk][1], qa_h[rt][kk][2], qa_h[rt][kk][3], bl0, bl1);
                    mma_bf16(acc4[rt], qa_l[rt][kk][0], qa_l[rt][kk][1], qa_l[rt][kk][2], qa_l[rt][kk][3], bh0, bh1);
                }
            }
            int s0 = c * 128 + nt * 8 + 2 * l3;
            int e0 = endsI[s0], e1 = endsI[s0 + 1];
            #pragma unroll
            for (int rt = 0; rt < 2; rt++) {
                int ra = rt * 16 + g, rb = ra + 8;
                Ls[ra * LSTR + s0]     = (e0 <= t0 + ra + 1) ? acc4[rt][0] * SCALE_ : -1e30f;
                Ls[ra * LSTR + s0 + 1] = (e1 <= t0 + ra + 1) ? acc4[rt][1] * SCALE_ : -1e30f;
                Ls[rb * LSTR + s0]     = (e0 <= t0 + rb + 1) ? acc4[rt][2] * SCALE_ : -1e30f;
                Ls[rb * LSTR + s0 + 1] = (e1 <= t0 + rb + 1) ? acc4[rt][3] * SCALE_ : -1e30f;
            }
        }
        __syncthreads();
    }

    stageV(cl[0], 0); CP_COMMIT();

    // ---- tail logits ----
    {
        #pragma unroll
        for (int ti = 0; ti < 4; ti++) {
            int tq = wid * 4 + ti;
            const float* ktp = Kt + ((size_t)h * T_ + t0 + tq) * 64;
            float p = Qs[tq * 64 + lane] * ktp[lane]
                    + Qs[tq * 64 + lane + 32] * ktp[lane + 32];
            #pragma unroll
            for (int o = 16; o; o >>= 1) p += __shfl_xor_sync(0xffffffffu, p, o);
            if (lane == 0) Ls[tq * LSTR + 1023] = p * SCALE_;
        }
    }
    __syncthreads();

    // ---- softmax (full 1024 cols, R14-proven form) ----
    {
        for (int ti = 0; ti < 4; ti++) {
            float* row = Ls + (wid * 4 + ti) * LSTR;
            float m = -1e30f;
            for (int s = lane; s < 1024; s += 32) m = fmaxf(m, row[s]);
            #pragma unroll
            for (int o = 16; o; o >>= 1) m = fmaxf(m, __shfl_xor_sync(0xffffffffu, m, o));
            float sum = 0.f;
            for (int s = lane; s < 1024; s += 32) {
                float e = expf(row[s] - m);
                row[s] = e;
                sum += e;
            }
            #pragma unroll
            for (int o = 16; o; o >>= 1) sum += __shfl_xor_sync(0xffffffffu, sum, o);
            float inv = 1.f / sum;
            for (int s = lane; s < 1024; s += 32) row[s] *= inv;
        }
    }
    __syncthreads();
    if (tid < 32) { tailw[tid] = Ls[tid * LSTR + 1023]; Ls[tid * LSTR + 1023] = 0.f; }
    __syncthreads();

    // ---- AV over active chunks (skipped chunks contribute exactly 0) ----
    float oacc[2][4] = {{0.f,0.f,0.f,0.f},{0.f,0.f,0.f,0.f}};
    for (int ci = 0; ci < nc; ci++) {
        int c = cl[ci];
        int buf = ci & 1;
        if (ci + 1 < nc) { stageV(cl[ci + 1], buf ^ 1); CP_COMMIT(); CP_WAIT1(); }
        else CP_WAIT0();
        __syncthreads();
        const uint32_t* Vh = (const uint32_t*)(smem + AT_BUF + buf * AT_BSTR);
        const uint32_t* Vl = Vh + 18432 / 4;
        #pragma unroll
        for (int kk = 0; kk < 8; kk++) {
            int kb = c * 128 + kk * 16 + 2 * l3;
            int d0 = wid * 8 + g;
            uint32_t bh0 = Vh[(kk * 8 + l3) * 72 + d0];
            uint32_t bh1 = Vh[(kk * 8 + l3 + 4) * 72 + d0];
            uint32_t bl0 = Vl[(kk * 8 + l3) * 72 + d0];
            uint32_t bl1 = Vl[(kk * 8 + l3 + 4) * 72 + d0];
            #pragma unroll
            for (int rt = 0; rt < 2; rt++) {
                int rb = rt * 16;
                float2 pa = *(const float2*)&Ls[(rb + g) * LSTR + kb];
                float2 pb = *(const float2*)&Ls[(rb + g) * LSTR + kb + 8];
                float2 pc = *(const float2*)&Ls[(rb + g + 8) * LSTR + kb];
                float2 pd = *(const float2*)&Ls[(rb + g + 8) * LSTR + kb + 8];
                uint32_t a0h, a0l, a1h, a1l, a2h, a2l, a3h, a3l;
                split2(pa.x, pa.y, a0h, a0l);
                split2(pc.x, pc.y, a1h, a1l);
                split2(pb.x, pb.y, a2h, a2l);
                split2(pd.x, pd.y, a3h, a3l);
                mma_bf16(oacc[rt], a0h, a1h, a2h, a3h, bh0, bh1);
                mma_bf16(oacc[rt], a0h, a1h, a2h, a3h, bl0, bl1);
                mma_bf16(oacc[rt], a0l, a1l, a2l, a3l, bh0, bh1);
            }
        }
        __syncthreads();
    }

    // ---- epilogue ----
    {
        int d0 = wid * 8 + 2 * l3;
        #pragma unroll
        for (int rt = 0; rt < 2; rt++) {
            int ra = rt * 16 + g, rb = ra + 8;
            float tw0 = tailw[ra], tw1 = tailw[rb];
            const float* vt0 = Vt + ((size_t)h * T_ + t0 + ra) * 64;
            const float* vt1 = Vt + ((size_t)h * T_ + t0 + rb) * 64;
            float* o0 = attout + (size_t)(t0 + ra) * C_ + h * 64 + d0;
            float* o1 = attout + (size_t)(t0 + rb) * C_ + h * 64 + d0;
            o0[0] = oacc[rt][0] + tw0 * vt0[d0];
            o0[1] = oacc[rt][1] + tw0 * vt0[d0 + 1];
            o1[0] = oacc[rt][2] + tw1 * vt1[d0];
            o1[1] = oacc[rt][3] + tw1 * vt1[d0 + 1];
        }
    }
}

extern "C" void kernel_launch(void* const* d_in, const int* in_sizes, int n_in,
                              void* d_out, int out_size) {
    const float* x   = (const float*)d_in[0];
    const float* Wq  = (const float*)d_in[1];
    const float* Wk  = (const float*)d_in[2];
    const float* Wv  = (const float*)d_in[3];
    const float* Wks = (const float*)d_in[4];
    const float* bks = (const float*)d_in[5];
    const float* Wvs = (const float*)d_in[6];
    const float* bvs = (const float*)d_in[7];
    const float* Wc  = (const float*)d_in[8];
    const float* bc  = (const float*)d_in[9];
    float* out = (float*)d_out;

    void *pq, *pk, *pv, *pG, *pWfh, *pWfl;
    void *pWqh, *pWql, *pWkh, *pWkl, *pWvh, *pWvl, *pWch, *pWcl;
    void *pKt, *pVt, *pKs, *pVs, *pKph, *pKpl, *pVph, *pVpl, *pCT, *pAtt;
    cudaGetSymbolAddress(&pq, g_q);     cudaGetSymbolAddress(&pk, g_k);
    cudaGetSymbolAddress(&pv, g_v);     cudaGetSymbolAddress(&pG, g_G);
    cudaGetSymbolAddress(&pWfh, g_Wfh); cudaGetSymbolAddress(&pWfl, g_Wfl);
    cudaGetSymbolAddress(&pWqh, g_Wqh); cudaGetSymbolAddress(&pWql, g_Wql);
    cudaGetSymbolAddress(&pWkh, g_Wkh); cudaGetSymbolAddress(&pWkl, g_Wkl);
    cudaGetSymbolAddress(&pWvh, g_Wvh); cudaGetSymbolAddress(&pWvl, g_Wvl);
    cudaGetSymbolAddress(&pWch, g_Wch); cudaGetSymbolAddress(&pWcl, g_Wcl);
    cudaGetSymbolAddress(&pKt, g_Kt);   cudaGetSymbolAddress(&pVt, g_Vt);
    cudaGetSymbolAddress(&pKs, g_Ks);   cudaGetSymbolAddress(&pVs, g_Vs);
    cudaGetSymbolAddress(&pKph, g_Kph); cudaGetSymbolAddress(&pKpl, g_Kpl);
    cudaGetSymbolAddress(&pVph, g_Vph); cudaGetSymbolAddress(&pVpl, g_Vpl);
    cudaGetSymbolAddress(&pCT, g_CT);   cudaGetSymbolAddress(&pAtt, g_att);

    cudaFuncSetAttribute(gemm_tc<0,1>, cudaFuncAttributeMaxDynamicSharedMemorySize, GT_SMEM);
    cudaFuncSetAttribute(gemm_qkv,     cudaFuncAttributeMaxDynamicSharedMemorySize, GT_SMEM);
    cudaFuncSetAttribute(gproj_mma,    cudaFuncAttributeMaxDynamicSharedMemorySize, GP_SMEM);
    cudaFuncSetAttribute(attn_mma,     cudaFuncAttributeMaxDynamicSharedMemorySize, AT_SMEM);

    split_wf<<<(2048*128)/256, 256>>>(Wks, Wvs, (uint32_t*)pWfh, (uint32_t*)pWfl);
    split_w4<<<dim3((384*C_ + 255)/256, 4), 256>>>(Wq, Wk, Wv, Wc,
        (uint32_t*)pWqh, (uint32_t*)pWql, (uint32_t*)pWkh, (uint32_t*)pWkl,
        (uint32_t*)pWvh, (uint32_t*)pWvl, (uint32_t*)pWch, (uint32_t*)pWcl);

    gemm_qkv<<<dim3(18, T_/128), 256, GT_SMEM>>>(x,
        (const uint32_t*)pWqh, (const uint32_t*)pWql,
        (const uint32_t*)pWkh, (const uint32_t*)pWkl,
        (const uint32_t*)pWvh, (const uint32_t*)pWvl,
        (float*)pq, (float*)pk, (float*)pv);

    gproj_mma<<<dim3(R_/128, 2), 256, GP_SMEM>>>((const float*)pk, (const float*)pv,
                                                 (const uint32_t*)pWfh, (const uint32_t*)pWfl,
                                                 (float*)pG);

    scan_kernel<<<dim3(8, NH_, 2), 64>>>((const float*)pG, bks, bvs,
        (float*)pKt, (float*)pVt, (float*)pKs, (float*)pVs, (float*)pCT);
    hilevel_kernel<<<dim3(NH_, 2), 64>>>((const float*)pCT, bks, bvs,
        (float*)pKs, (float*)pVs);

    pack_kv<<<dim3((NH_*1024*32)/256, 2), 256>>>((const float*)pKs, (const float*)pVs,
        (uint32_t*)pKph, (uint32_t*)pKpl, (uint32_t*)pVph, (uint32_t*)pVpl);

    attn_mma<<<dim3(T_/32, NH_), 256, AT_SMEM>>>((const float*)pq,
        (const uint32_t*)pKph, (const uint32_t*)pKpl,
        (const uint32_t*)pVph, (const uint32_t*)pVpl,
        (const float*)pKt, (const float*)pVt, (float*)pAtt);

    gemm_tc<0,1><<<dim3(C_/128, T_/128), 256, GT_SMEM>>>((const float*)pAtt,
        (const uint32_t*)pWch, (const uint32_t*)pWcl, bc, out, T_, C_, C_);
}